// round 1
// baseline (speedup 1.0000x reference)
#include <cuda_runtime.h>
#include <cuda_bf16.h>
#include <math.h>

// Problem constants (fixed-shape problem)
#define BB   4
#define NN   32768
#define KK   16
#define CIN  32
#define HH   32
#define COUT 32
#define PP   3

#define GTOT (BB * NN)          // 131072 nodes
#define ETOT (BB * NN * KK)     // 2097152 edges
#define MELEMS (GTOT * HH)      // 4194304 floats (16 MB)

// Scratch: __device__ globals (no allocation allowed)
__device__ float g_m[MELEMS];    // m[node,h] = (W1x+b1)*gw*sqrt((bw/pi)^3)
__device__ float g_acc[MELEMS];  // segment-sum accumulator

// ---------------------------------------------------------------------------
// Zero the accumulator (needed every launch; out poisoned, acc reused)
// ---------------------------------------------------------------------------
__global__ void zero_acc_kernel() {
    int i = blockIdx.x * blockDim.x + threadIdx.x;     // MELEMS/4 threads
    reinterpret_cast<float4*>(g_acc)[i] = make_float4(0.f, 0.f, 0.f, 0.f);
}

// ---------------------------------------------------------------------------
// GEMM1 fused: m[g,h] = (sum_c W1[h,c]*x[b,c,n] + b1[h]) * gw[g] * sqrt((bw[h]/pi)^3)
// One thread per node. x reads coalesced along n. W1 transposed in smem so the
// inner loop uses LDS.128.
// ---------------------------------------------------------------------------
__global__ void gemm1_kernel(const float* __restrict__ x,
                             const float* __restrict__ gw,
                             const float* __restrict__ W1,
                             const float* __restrict__ b1,
                             const float* __restrict__ bw) {
    __shared__ float sWT[CIN * HH];   // sWT[c*HH + h] = W1[h*CIN + c]
    __shared__ float sbc[HH];
    __shared__ float scc[HH];
    int t = threadIdx.x;
    for (int i = t; i < CIN * HH; i += blockDim.x) {
        int h = i & (HH - 1);
        int c = i >> 5;
        sWT[i] = W1[h * CIN + c];
    }
    if (t < HH) {
        sbc[t] = b1[t];
        float w = bw[t];
        float r = w * 0.3183098861837907f;   // bw/pi
        scc[t] = sqrtf(r * r * r);
    }
    __syncthreads();

    int g = blockIdx.x * blockDim.x + t;    // node id in [0, GTOT)
    int b = g >> 15;                        // NN = 2^15
    int n = g & (NN - 1);
    const float* xb = x + (size_t)b * CIN * NN + n;

    float acc[HH];
#pragma unroll
    for (int h = 0; h < HH; h++) acc[h] = 0.f;

#pragma unroll
    for (int c = 0; c < CIN; c++) {
        float xv = xb[(size_t)c * NN];      // coalesced across the warp
        const float4* wrow = reinterpret_cast<const float4*>(sWT + c * HH);
#pragma unroll
        for (int h4 = 0; h4 < HH / 4; h4++) {
            float4 wv = wrow[h4];
            acc[h4 * 4 + 0] += wv.x * xv;
            acc[h4 * 4 + 1] += wv.y * xv;
            acc[h4 * 4 + 2] += wv.z * xv;
            acc[h4 * 4 + 3] += wv.w * xv;
        }
    }

    float w = gw[g];
    float4* mo = reinterpret_cast<float4*>(g_m + (size_t)g * HH);
#pragma unroll
    for (int h4 = 0; h4 < HH / 4; h4++) {
        float4 v;
        v.x = (acc[h4 * 4 + 0] + sbc[h4 * 4 + 0]) * w * scc[h4 * 4 + 0];
        v.y = (acc[h4 * 4 + 1] + sbc[h4 * 4 + 1]) * w * scc[h4 * 4 + 1];
        v.z = (acc[h4 * 4 + 2] + sbc[h4 * 4 + 2]) * w * scc[h4 * 4 + 2];
        v.w = (acc[h4 * 4 + 3] + sbc[h4 * 4 + 3]) * w * scc[h4 * 4 + 3];
        mo[h4] = v;
    }
}

// ---------------------------------------------------------------------------
// Edge kernel: one warp per edge, lane = hidden channel.
// acc[dst,h] += m[src,h] * exp(-bw[h]*d2)
// m load is a coalesced 128B transaction; grid loads are warp-broadcast;
// atomicAdd compiles to RED.E.ADD.F32 (no return), 32 consecutive addresses.
// ---------------------------------------------------------------------------
__global__ void edge_kernel(const int* __restrict__ es,
                            const int* __restrict__ ed,
                            const float* __restrict__ grid,
                            const float* __restrict__ bw) {
    int gid  = blockIdx.x * blockDim.x + threadIdx.x;
    int e    = gid >> 5;                 // one warp per edge; grid sized exactly
    int lane = threadIdx.x & 31;

    float bwl = __ldg(bw + lane);

    int b   = e >> 19;                   // NN*KK = 524288 = 2^19
    int off = b << 15;                   // b * NN
    int s   = __ldg(es + e) + off;
    int d   = __ldg(ed + e) + off;

    const float* gs = grid + s * PP;     // warp-broadcast loads
    const float* gd = grid + d * PP;
    float dx = gs[0] - gd[0];
    float dy = gs[1] - gd[1];
    float dz = gs[2] - gd[2];
    float d2 = dx * dx + dy * dy + dz * dz;

    float mv  = __ldg(g_m + (size_t)s * HH + lane);   // coalesced 128B
    float val = mv * __expf(-bwl * d2);               // MUFU EX2

    atomicAdd(g_acc + (size_t)d * HH + lane, val);    // RED.E.ADD.F32
}

// ---------------------------------------------------------------------------
// GEMM2: out[b,o,n] = sum_h W2[o,h]*acc[g,h] + b2[o]
// One thread per node; output writes coalesced along n for each o.
// ---------------------------------------------------------------------------
__global__ void gemm2_kernel(const float* __restrict__ W2,
                             const float* __restrict__ b2,
                             float* __restrict__ out) {
    __shared__ float sW2[COUT * HH];     // row-major (o,h), matches input layout
    __shared__ float sb2[COUT];
    int t = threadIdx.x;
    for (int i = t; i < COUT * HH; i += blockDim.x) sW2[i] = W2[i];
    if (t < COUT) sb2[t] = b2[t];
    __syncthreads();

    int g = blockIdx.x * blockDim.x + t;
    int b = g >> 15;
    int n = g & (NN - 1);

    float a[HH];
    const float4* av = reinterpret_cast<const float4*>(g_acc + (size_t)g * HH);
#pragma unroll
    for (int i = 0; i < HH / 4; i++) {
        float4 v = av[i];
        a[4 * i + 0] = v.x;
        a[4 * i + 1] = v.y;
        a[4 * i + 2] = v.z;
        a[4 * i + 3] = v.w;
    }

    float* ob = out + (size_t)b * COUT * NN + n;
#pragma unroll
    for (int o = 0; o < COUT; o++) {
        const float4* wr = reinterpret_cast<const float4*>(sW2 + o * HH);
        float s0 = 0.f, s1 = 0.f, s2 = 0.f, s3 = 0.f;
#pragma unroll
        for (int i = 0; i < HH / 4; i++) {
            float4 wv = wr[i];
            s0 += wv.x * a[4 * i + 0];
            s1 += wv.y * a[4 * i + 1];
            s2 += wv.z * a[4 * i + 2];
            s3 += wv.w * a[4 * i + 3];
        }
        ob[(size_t)o * NN] = (s0 + s1) + (s2 + s3) + sb2[o];
    }
}

// ---------------------------------------------------------------------------
// Launcher
// inputs: 0:x 1:grid 2:grid_weight 3:edge_src 4:edge_dst 5:W1 6:b1 7:W2 8:b2 9:baseweight
// ---------------------------------------------------------------------------
extern "C" void kernel_launch(void* const* d_in, const int* in_sizes, int n_in,
                              void* d_out, int out_size) {
    const float* x    = (const float*)d_in[0];
    const float* grid = (const float*)d_in[1];
    const float* gw   = (const float*)d_in[2];
    const int*   es   = (const int*)d_in[3];
    const int*   ed   = (const int*)d_in[4];
    const float* W1   = (const float*)d_in[5];
    const float* b1   = (const float*)d_in[6];
    const float* W2   = (const float*)d_in[7];
    const float* b2   = (const float*)d_in[8];
    const float* bw   = (const float*)d_in[9];
    float* out = (float*)d_out;

    // 1) zero accumulator: MELEMS/4 float4 stores
    zero_acc_kernel<<<(MELEMS / 4) / 256, 256>>>();

    // 2) fused fc1 + gauss-normalization + grid_weight -> g_m
    gemm1_kernel<<<GTOT / 256, 256>>>(x, gw, W1, b1, bw);

    // 3) edge scatter: one warp per edge
    edge_kernel<<<(ETOT * 32) / 256, 256>>>(es, ed, grid, bw);

    // 4) fc2 + transpose to (B, COUT, N)
    gemm2_kernel<<<GTOT / 256, 256>>>(W2, b2, out);
}

// round 2
// speedup vs baseline: 2.2233x; 2.2233x over previous
#include <cuda_runtime.h>
#include <cuda_bf16.h>
#include <math.h>

// Fixed problem shape
#define BB   4
#define NN   32768
#define KK   16
#define CIN  32
#define HH   32
#define COUT 32
#define PP   3

#define GTOT (BB * NN)          // 131072 nodes
#define ETOT (BB * NN * KK)     // 2097152 edges
#define MELEMS (GTOT * HH)      // 4194304 floats (16 MB)

// Scratch (__device__ globals; no allocation allowed)
__device__ float  g_m[MELEMS];     // m[node,h] = (W1x+b1)*gw*sqrt((bw/pi)^3)
__device__ float  g_acc[MELEMS];   // segment-sum accumulator
__device__ float4 g_grid4[GTOT];   // packed grid coords (x,y,z,0)

// Small weights live in constant memory -> uniform-path LDCU on sm_103a
__constant__ float cW1[HH * CIN];
__constant__ float cb1[HH];
__constant__ float cbw[HH];
__constant__ float cW2[COUT * HH];
__constant__ float cb2[COUT];

// ---------------------------------------------------------------------------
// gemm1 fused: per node g
//   m[g,h]   = (sum_c W1[h,c]*x[b,c,n] + b1[h]) * gw[g] * sqrt((bw[h]/pi)^3)
//   acc[g,:] = 0
//   grid4[g] = packed (x,y,z)
// x reads coalesced along n; weights via constant (LDCU).
// ---------------------------------------------------------------------------
__global__ void gemm1_kernel(const float* __restrict__ x,
                             const float* __restrict__ gw,
                             const float* __restrict__ grid) {
    int g = blockIdx.x * blockDim.x + threadIdx.x;   // node id
    int b = g >> 15;                                 // NN = 2^15
    int n = g & (NN - 1);
    const float* xb = x + (size_t)b * CIN * NN + n;

    float acc[HH];
#pragma unroll
    for (int h = 0; h < HH; h++) acc[h] = 0.f;

#pragma unroll
    for (int c = 0; c < CIN; c++) {
        float xv = xb[(size_t)c * NN];               // coalesced
#pragma unroll
        for (int h = 0; h < HH; h++)
            acc[h] += cW1[h * CIN + c] * xv;         // LDCU + FFMA
    }

    float w = gw[g];
    float4* mo = reinterpret_cast<float4*>(g_m + (size_t)g * HH);
    float4* ao = reinterpret_cast<float4*>(g_acc + (size_t)g * HH);
#pragma unroll
    for (int h4 = 0; h4 < HH / 4; h4++) {
        float4 v;
#pragma unroll
        for (int j = 0; j < 4; j++) {
            int h = h4 * 4 + j;
            float r = cbw[h] * 0.3183098861837907f;  // bw/pi
            float scale = sqrtf(r * r * r);
            float m = (acc[h] + cb1[h]) * w * scale;
            ((float*)&v)[j] = m;
        }
        mo[h4] = v;
        ao[h4] = make_float4(0.f, 0.f, 0.f, 0.f);
    }

    // pack grid coords
    const float* gp = grid + (size_t)g * PP;
    g_grid4[g] = make_float4(gp[0], gp[1], gp[2], 0.f);
}

// ---------------------------------------------------------------------------
// Edge kernel: each warp owns 32 edges.
// Phase 1 (lane = edge): coalesced es/ed loads, float4 grid gathers (MLP=64),
//   d2 per lane, stage (s*32, d*32, d2) into smem.
// Phase 2 (lane = channel): 32 iters; broadcast LDS.128 of the staged tuple,
//   random-row m gather (coalesced 128B across warp), MUFU EX2, RED.E.ADD.
// ---------------------------------------------------------------------------
__global__ void edge_kernel(const int* __restrict__ es,
                            const int* __restrict__ ed,
                            const float* __restrict__ bw) {
    __shared__ float4 stage[8][32];                  // 8 warps/block
    int tid  = blockIdx.x * blockDim.x + threadIdx.x;
    int lane = threadIdx.x & 31;
    int w    = threadIdx.x >> 5;

    // ---- phase 1: this lane's edge ----
    int e   = tid;                                   // grid sized to ETOT
    int b   = e >> 19;                               // NN*KK = 2^19
    int off = b << 15;                               // b * NN
    int s   = __ldg(es + e) + off;
    int d   = __ldg(ed + e) + off;

    float4 gs = g_grid4[s];
    float4 gd = g_grid4[d];
    float dx = gs.x - gd.x;
    float dy = gs.y - gd.y;
    float dz = gs.z - gd.z;
    float d2 = dx * dx + dy * dy + dz * dz;

    stage[w][lane] = make_float4(__int_as_float(s * HH),
                                 __int_as_float(d * HH), d2, 0.f);
    __syncwarp();

    // ---- phase 2: lane = hidden channel ----
    // exp(-bw*d2) = ex2(nb*d2), nb = -bw*log2(e)
    float nb = __ldg(bw + lane) * (-1.4426950408889634f);

#pragma unroll 8
    for (int i = 0; i < 32; i++) {
        float4 p  = stage[w][i];                     // broadcast LDS.128
        int   si  = __float_as_int(p.x);
        int   di  = __float_as_int(p.y);
        float d2i = p.z;
        float mv  = __ldg(g_m + si + lane);          // coalesced 128B row
        float ex;
        asm("ex2.approx.f32 %0, %1;" : "=f"(ex) : "f"(nb * d2i));
        atomicAdd(g_acc + di + lane, mv * ex);       // RED.E.ADD.F32
    }
}

// ---------------------------------------------------------------------------
// gemm2: out[b,o,n] = sum_h W2[o,h]*acc[g,h] + b2[o]
// W2/b2 via constant (LDCU); acc row via 4x LDG.128; outputs coalesced.
// ---------------------------------------------------------------------------
__global__ void gemm2_kernel(float* __restrict__ out) {
    int g = blockIdx.x * blockDim.x + threadIdx.x;
    int b = g >> 15;
    int n = g & (NN - 1);

    float a[HH];
    const float4* av = reinterpret_cast<const float4*>(g_acc + (size_t)g * HH);
#pragma unroll
    for (int i = 0; i < HH / 4; i++) {
        float4 v = av[i];
        a[4 * i + 0] = v.x;
        a[4 * i + 1] = v.y;
        a[4 * i + 2] = v.z;
        a[4 * i + 3] = v.w;
    }

    float* ob = out + (size_t)b * COUT * NN + n;
#pragma unroll
    for (int o = 0; o < COUT; o++) {
        float s = cb2[o];
#pragma unroll
        for (int h = 0; h < HH; h++)
            s += cW2[o * HH + h] * a[h];             // LDCU + FFMA
        ob[(size_t)o * NN] = s;
    }
}

// ---------------------------------------------------------------------------
// Launcher
// inputs: 0:x 1:grid 2:grid_weight 3:edge_src 4:edge_dst 5:W1 6:b1 7:W2 8:b2 9:baseweight
// ---------------------------------------------------------------------------
extern "C" void kernel_launch(void* const* d_in, const int* in_sizes, int n_in,
                              void* d_out, int out_size) {
    const float* x    = (const float*)d_in[0];
    const float* grid = (const float*)d_in[1];
    const float* gw   = (const float*)d_in[2];
    const int*   es   = (const int*)d_in[3];
    const int*   ed   = (const int*)d_in[4];
    const float* W1   = (const float*)d_in[5];
    const float* b1   = (const float*)d_in[6];
    const float* W2   = (const float*)d_in[7];
    const float* b2   = (const float*)d_in[8];
    const float* bw   = (const float*)d_in[9];
    float* out = (float*)d_out;

    // Stage small weights into constant memory (D2D, graph-capturable)
    cudaMemcpyToSymbolAsync(cW1, W1, HH * CIN * sizeof(float), 0,
                            cudaMemcpyDeviceToDevice, 0);
    cudaMemcpyToSymbolAsync(cb1, b1, HH * sizeof(float), 0,
                            cudaMemcpyDeviceToDevice, 0);
    cudaMemcpyToSymbolAsync(cbw, bw, HH * sizeof(float), 0,
                            cudaMemcpyDeviceToDevice, 0);
    cudaMemcpyToSymbolAsync(cW2, W2, COUT * HH * sizeof(float), 0,
                            cudaMemcpyDeviceToDevice, 0);
    cudaMemcpyToSymbolAsync(cb2, b2, COUT * sizeof(float), 0,
                            cudaMemcpyDeviceToDevice, 0);

    // 1) fused fc1 + gauss-norm + grid_weight -> g_m ; zero g_acc ; pack grid
    gemm1_kernel<<<GTOT / 256, 256>>>(x, gw, grid);

    // 2) edge scatter: 32 edges per warp, two-phase
    edge_kernel<<<ETOT / 256, 256>>>(es, ed, bw);

    // 3) fc2 + transpose to (B, COUT, N)
    gemm2_kernel<<<GTOT / 256, 256>>>(out);
}